// round 2
// baseline (speedup 1.0000x reference)
#include <cuda_runtime.h>
#include <math.h>

#define B_    8
#define L_    999
#define C_    768
#define C2_   384
#define H_    8
#define HD_   48
#define G_    2
#define K_    3
#define DCIN_ 96
#define PJIN_ 96
#define M_    (B_*L_)          /* 7992 tokens */
#define SCALE_ 0.14433756729740643f
#define EPS_   1e-5f

__device__ __forceinline__ float gelu_f(float v) {
    return 0.5f * v * (1.0f + erff(v * 0.7071067811865475f));
}

// ---------------- scratch (device globals; no allocation allowed) ----------------
__device__ float g_q    [(size_t)M_*C2_];
__device__ float g_kvin [(size_t)M_*C2_];
__device__ float g_kv   [(size_t)M_*C_];
__device__ float g_xc   [(size_t)M_*C_];   // concat(dynconv_out, attn_out-scrambled), residual
__device__ float g_t1   [(size_t)M_*C_];
__device__ float g_t2   [(size_t)M_*PJIN_];
__device__ float g_t3   [(size_t)M_*C_];
__device__ float g_pooled[B_*K_*C2_];
__device__ float g_wdyn [B_*C2_*K_];
__device__ float g_bdyn [B_*C2_];
__device__ float g_ps   [64*C_];
__device__ float g_ps2  [64*C_];
__device__ float g_an   [C_];
__device__ float g_bn   [C_];

// ---------------- stage 1: pooled means for dynamic-conv MLP ----------------
__global__ void pooled_kernel(const float* __restrict__ x) {
    int b  = blockIdx.x / K_;
    int kk = blockIdx.x % K_;
    int c  = threadIdx.x;                  // 384
    const float* xb = x + (size_t)b*L_*C_ + c;
    int l0 = kk*333;
    float s = 0.f;
    for (int l = l0; l < l0+333; l++) s += xb[(size_t)l*C_];
    g_pooled[(b*K_+kk)*C2_ + c] = s * (1.0f/333.0f);
}

// ---------------- stage 2: dynamic-conv score MLP + softmax over G ----------------
__global__ void dcmlp_kernel(const float* __restrict__ p1w, const float* __restrict__ p1b,
                             const float* __restrict__ p2w, const float* __restrict__ p2b,
                             const float* __restrict__ dcw, const float* __restrict__ dcb) {
    int b   = blockIdx.x;
    int tid = threadIdx.x;                 // 384
    __shared__ float col[4][C2_];
    __shared__ float hid[4][DCIN_];
    __shared__ float sc [4][2*C2_];
    {
        float c0 = g_pooled[(b*3+0)*C2_+tid];
        float c1 = g_pooled[(b*3+1)*C2_+tid];
        float c2 = g_pooled[(b*3+2)*C2_+tid];
        col[0][tid]=c0; col[1][tid]=c1; col[2][tid]=c2;
        col[3][tid]=(c0+c1+c2)*(1.0f/3.0f);      // xm = mean over full L
    }
    __syncthreads();
    {   // hidden = gelu(p1w @ col + p1b) : 4 cols x 96
        int kk = tid / DCIN_;
        int i  = tid % DCIN_;
        float s = p1b[i];
        const float* wr = p1w + (size_t)i*C2_;
        #pragma unroll 8
        for (int c = 0; c < C2_; c++) s += wr[c]*col[kk][c];
        hid[kk][i] = gelu_f(s);
    }
    __syncthreads();
    for (int t = tid; t < 4*768; t += 384) {   // sc = p2w @ hid + p2b : 4 cols x 768
        int kk = t / 768, o = t % 768;
        float s = p2b[o];
        const float* wr = p2w + (size_t)o*DCIN_;
        #pragma unroll 8
        for (int i = 0; i < DCIN_; i++) s += wr[i]*hid[kk][i];
        sc[kk][o] = s;
    }
    __syncthreads();
    {   // softmax over G=2 (pairs c, C2+c), combine with dc_weight / dc_bias
        int c = tid;
        #pragma unroll
        for (int kk = 0; kk < 3; kk++) {
            float e0 = sc[kk][c], e1 = sc[kk][C2_+c];
            float mx = fmaxf(e0,e1);
            float a0 = expf(e0-mx), a1 = expf(e1-mx);
            float inv = 1.f/(a0+a1);
            g_wdyn[(b*C2_+c)*3+kk] = (a0*dcw[c*3+kk] + a1*dcw[(C2_+c)*3+kk])*inv;
        }
        float e0 = sc[3][c], e1 = sc[3][C2_+c];
        float mx = fmaxf(e0,e1);
        float a0 = expf(e0-mx), a1 = expf(e1-mx);
        g_bdyn[b*C2_+c] = (a0*dcb[c] + a1*dcb[C2_+c])/(a0+a1);
    }
}

// ---------------- stage 3: dynamic depthwise conv -> xc[:, :, 0:384] ----------------
__global__ void dconv_kernel(const float* __restrict__ x) {
    int b = blockIdx.y, chunk = blockIdx.x;
    int c = threadIdx.x;                   // 384
    int l0 = chunk*63;
    int l1 = min(l0+63, L_);
    if (l0 >= L_) return;
    float w0 = g_wdyn[(b*C2_+c)*3+0];
    float w1 = g_wdyn[(b*C2_+c)*3+1];
    float w2 = g_wdyn[(b*C2_+c)*3+2];
    float bb = g_bdyn[b*C2_+c];
    const float* xb = x    + (size_t)b*L_*C_ + c;
    float*       yb = g_xc + (size_t)b*L_*C_ + c;
    float xm1 = (l0 > 0) ? xb[(size_t)(l0-1)*C_] : 0.f;
    float x0  = xb[(size_t)l0*C_];
    for (int l = l0; l < l1; l++) {
        float xp1 = (l+1 < L_) ? xb[(size_t)(l+1)*C_] : 0.f;
        yb[(size_t)l*C_] = xm1*w0 + x0*w1 + xp1*w2 + bb;
        xm1 = x0; x0 = xp1;
    }
}

// ---------------- stage 4: kv_in = dw3(x2, lcw, lcb) + x2 ----------------
__global__ void kvin_kernel(const float* __restrict__ x,
                            const float* __restrict__ lcw, const float* __restrict__ lcb) {
    int b = blockIdx.y, chunk = blockIdx.x;
    int c = threadIdx.x;                   // 384
    int l0 = chunk*63;
    int l1 = min(l0+63, L_);
    if (l0 >= L_) return;
    float w0 = lcw[c*3], w1 = lcw[c*3+1], w2 = lcw[c*3+2], bb = lcb[c];
    const float* xb = x      + (size_t)b*L_*C_ + C2_ + c;
    float*       yb = g_kvin + (size_t)b*L_*C2_ + c;
    float xm1 = (l0 > 0) ? xb[(size_t)(l0-1)*C_] : 0.f;
    float x0  = xb[(size_t)l0*C_];
    for (int l = l0; l < l1; l++) {
        float xp1 = (l+1 < L_) ? xb[(size_t)(l+1)*C_] : 0.f;
        yb[(size_t)l*C2_] = xm1*w0 + x0*w1 + xp1*w2 + bb + x0;
        xm1 = x0; x0 = xp1;
    }
}

// ---------------- generic tiled GEMM: C[m,n] = sum_k a(A[m,k]) * W[n,k] + bias[n] ----
__global__ void gemm_kernel(const float* __restrict__ A, int lda,
                            const float* __restrict__ W,
                            const float* __restrict__ bias,
                            float* __restrict__ Cmat, int ldc,
                            int M, int N, int Kd,
                            const float* __restrict__ ascale,
                            const float* __restrict__ ashift,
                            int dogelu)
{
    __shared__ float As[64][17];
    __shared__ float Ws[64][17];
    int tid = threadIdx.x;                 // 256
    int tx = tid & 15, ty = tid >> 4;
    int m0 = blockIdx.x*64, n0 = blockIdx.y*64;
    float acc[4][4];
    #pragma unroll
    for (int i = 0; i < 4; i++)
        #pragma unroll
        for (int j = 0; j < 4; j++) acc[i][j] = 0.f;

    int r  = tid >> 2;
    int kq = (tid & 3) << 2;
    for (int k0 = 0; k0 < Kd; k0 += 16) {
        float4 av = make_float4(0.f,0.f,0.f,0.f);
        int gm = m0 + r;
        if (gm < M) av = *reinterpret_cast<const float4*>(A + (size_t)gm*lda + k0 + kq);
        if (ascale) {
            av.x = av.x*ascale[k0+kq+0] + ashift[k0+kq+0];
            av.y = av.y*ascale[k0+kq+1] + ashift[k0+kq+1];
            av.z = av.z*ascale[k0+kq+2] + ashift[k0+kq+2];
            av.w = av.w*ascale[k0+kq+3] + ashift[k0+kq+3];
        }
        float4 wv = make_float4(0.f,0.f,0.f,0.f);
        int gn = n0 + r;
        if (gn < N) wv = *reinterpret_cast<const float4*>(W + (size_t)gn*Kd + k0 + kq);
        __syncthreads();
        As[r][kq+0]=av.x; As[r][kq+1]=av.y; As[r][kq+2]=av.z; As[r][kq+3]=av.w;
        Ws[r][kq+0]=wv.x; Ws[r][kq+1]=wv.y; Ws[r][kq+2]=wv.z; Ws[r][kq+3]=wv.w;
        __syncthreads();
        #pragma unroll
        for (int k = 0; k < 16; k++) {
            float a0 = As[ty*4+0][k], a1 = As[ty*4+1][k];
            float a2 = As[ty*4+2][k], a3 = As[ty*4+3][k];
            float b0 = Ws[tx*4+0][k], b1 = Ws[tx*4+1][k];
            float b2 = Ws[tx*4+2][k], b3 = Ws[tx*4+3][k];
            acc[0][0]+=a0*b0; acc[0][1]+=a0*b1; acc[0][2]+=a0*b2; acc[0][3]+=a0*b3;
            acc[1][0]+=a1*b0; acc[1][1]+=a1*b1; acc[1][2]+=a1*b2; acc[1][3]+=a1*b3;
            acc[2][0]+=a2*b0; acc[2][1]+=a2*b1; acc[2][2]+=a2*b2; acc[2][3]+=a2*b3;
            acc[3][0]+=a3*b0; acc[3][1]+=a3*b1; acc[3][2]+=a3*b2; acc[3][3]+=a3*b3;
        }
    }
    #pragma unroll
    for (int i = 0; i < 4; i++) {
        int gm = m0 + ty*4 + i;
        if (gm >= M) continue;
        #pragma unroll
        for (int j = 0; j < 4; j++) {
            int gn = n0 + tx*4 + j;
            if (gn >= N) continue;
            float v = acc[i][j] + bias[gn];
            if (dogelu) v = gelu_f(v);
            Cmat[(size_t)gm*ldc + gn] = v;
        }
    }
}

// ---------------- stage 7: flash attention (fp32) -> xc[:, :, 384:768] ----------------
// IMPORTANT: reference does transpose(out,(0,1,3,2)).reshape(B,L,C2) which is a RAW
// flat reinterpretation of the (H,HD,L) channel-major buffer as (L,C2). Reproduce it:
// element (c = h*HD+d, l) -> flat = c*L + l -> writes xc[b, flat/C2, C2 + flat%C2].
__global__ void attn_kernel() {
    int qt = blockIdx.x;     // 16 q tiles of 64
    int h  = blockIdx.y;     // 8
    int b  = blockIdx.z;     // 8
    int tid = threadIdx.x;   // 256
    int r   = tid >> 2;      // q row within tile
    int sub = tid & 3;       // key sub-range
    __shared__ float qs[64][52];
    __shared__ float ks[64][52];
    __shared__ float vs[64][52];

    const float* qb = g_q  + (size_t)b*L_*C2_ + h*HD_;
    const float* kb = g_kv + (size_t)b*L_*C_  + h*HD_;
    const float* vb = kb + C2_;

    for (int i = tid; i < 64*HD_; i += 256) {
        int rr = i / HD_, d = i % HD_;
        int gl = qt*64 + rr;
        qs[rr][d] = (gl < L_) ? qb[(size_t)gl*C2_ + d] : 0.f;
    }

    float m = -1e30f, lsum = 0.f;
    float o[HD_];
    #pragma unroll
    for (int d = 0; d < HD_; d++) o[d] = 0.f;

    for (int kt = 0; kt < 16; kt++) {
        __syncthreads();
        for (int i = tid; i < 64*HD_; i += 256) {
            int rr = i / HD_, d = i % HD_;
            int gl = kt*64 + rr;
            if (gl < L_) {
                ks[rr][d] = kb[(size_t)gl*C_ + d];
                vs[rr][d] = vb[(size_t)gl*C_ + d];
            } else { ks[rr][d] = 0.f; vs[rr][d] = 0.f; }
        }
        __syncthreads();

        float s[16];
        #pragma unroll
        for (int j = 0; j < 16; j++) s[j] = 0.f;
        #pragma unroll
        for (int d4 = 0; d4 < HD_/4; d4++) {
            float4 qv = *reinterpret_cast<float4*>(&qs[r][d4*4]);
            #pragma unroll
            for (int j = 0; j < 16; j++) {
                float4 kk = *reinterpret_cast<float4*>(&ks[sub*16+j][d4*4]);
                s[j] += qv.x*kk.x + qv.y*kk.y + qv.z*kk.z + qv.w*kk.w;
            }
        }
        float smax = -1e30f;
        #pragma unroll
        for (int j = 0; j < 16; j++) {
            int gl = kt*64 + sub*16 + j;
            s[j] = (gl < L_) ? s[j]*SCALE_ : -1e30f;
            smax = fmaxf(smax, s[j]);
        }
        smax = fmaxf(smax, __shfl_xor_sync(0xffffffffu, smax, 1));
        smax = fmaxf(smax, __shfl_xor_sync(0xffffffffu, smax, 2));
        float mnew = fmaxf(m, smax);
        float corr = expf(m - mnew);
        lsum *= corr;
        #pragma unroll
        for (int d = 0; d < HD_; d++) o[d] *= corr;
        float lp = 0.f;
        #pragma unroll
        for (int j = 0; j < 16; j++) { s[j] = expf(s[j] - mnew); lp += s[j]; }
        lsum += lp;
        m = mnew;
        #pragma unroll
        for (int d4 = 0; d4 < HD_/4; d4++) {
            float o0 = o[d4*4+0], o1 = o[d4*4+1], o2 = o[d4*4+2], o3 = o[d4*4+3];
            #pragma unroll
            for (int j = 0; j < 16; j++) {
                float4 vv = *reinterpret_cast<float4*>(&vs[sub*16+j][d4*4]);
                o0 += s[j]*vv.x; o1 += s[j]*vv.y; o2 += s[j]*vv.z; o3 += s[j]*vv.w;
            }
            o[d4*4+0]=o0; o[d4*4+1]=o1; o[d4*4+2]=o2; o[d4*4+3]=o3;
        }
    }
    // combine across the 4 sub-threads of each row
    float lt = lsum;
    lt += __shfl_xor_sync(0xffffffffu, lt, 1);
    lt += __shfl_xor_sync(0xffffffffu, lt, 2);
    #pragma unroll
    for (int d = 0; d < HD_; d++) {
        float v = o[d];
        v += __shfl_xor_sync(0xffffffffu, v, 1);
        v += __shfl_xor_sync(0xffffffffu, v, 2);
        o[d] = v;
    }
    int gl = qt*64 + r;
    if (gl < L_) {
        float inv = 1.f/lt;
        float* xcb = g_xc + (size_t)b*L_*C_;
        #pragma unroll
        for (int d = 0; d < 12; d++) {
            int dd = sub*12 + d;
            int c  = h*HD_ + dd;
            int flat = c*L_ + gl;            // channel-major flat index
            int lp = flat / C2_;
            int cp = flat - lp*C2_;
            xcb[(size_t)lp*C_ + C2_ + cp] = o[dd]*inv;
        }
    }
}

// ---------------- stage 8a: t1 = gelu(dw3(xc)) + per-chunk BN1 partials ----------------
__global__ void pjdw_kernel(const float* __restrict__ dww, const float* __restrict__ dwb) {
    int b = blockIdx.y, chunk = blockIdx.x;   // 8 x 8
    int c = threadIdx.x;                      // 768
    int l0 = chunk*125, l1 = min(l0+125, L_);
    float w0 = dww[c*3], w1 = dww[c*3+1], w2 = dww[c*3+2], bb = dwb[c];
    const float* xb = g_xc + (size_t)b*L_*C_ + c;
    float*       yb = g_t1 + (size_t)b*L_*C_ + c;
    float s = 0.f, s2 = 0.f;
    float xm1 = (l0 > 0) ? xb[(size_t)(l0-1)*C_] : 0.f;
    float x0  = xb[(size_t)l0*C_];
    for (int l = l0; l < l1; l++) {
        float xp1 = (l+1 < L_) ? xb[(size_t)(l+1)*C_] : 0.f;
        float v = gelu_f(xm1*w0 + x0*w1 + xp1*w2 + bb);
        yb[(size_t)l*C_] = v;
        s += v; s2 += v*v;
        xm1 = x0; x0 = xp1;
    }
    int blk = b*8 + chunk;
    g_ps [blk*C_ + c] = s;
    g_ps2[blk*C_ + c] = s2;
}

// ---------------- deterministic BN stats: partials + finalize -> affine (a,b) ----------
__global__ void stats_partial_kernel(const float* __restrict__ X, int Cch) {
    int blk = blockIdx.x;                  // 64 chunks of 125 rows
    int c   = threadIdx.x;                 // Cch
    int r0 = blk*125, r1 = min(r0+125, M_);
    float s = 0.f, s2 = 0.f;
    for (int r = r0; r < r1; r++) {
        float v = X[(size_t)r*Cch + c];
        s += v; s2 += v*v;
    }
    g_ps [blk*Cch + c] = s;
    g_ps2[blk*Cch + c] = s2;
}

__global__ void stats_finalize_kernel(int nblk, int Cch,
                                      const float* __restrict__ gam,
                                      const float* __restrict__ bet) {
    int c = blockIdx.x*blockDim.x + threadIdx.x;
    if (c >= Cch) return;
    double s = 0.0, s2 = 0.0;
    for (int i = 0; i < nblk; i++) { s += (double)g_ps[i*Cch+c]; s2 += (double)g_ps2[i*Cch+c]; }
    double mean = s / (double)M_;
    double var  = s2 / (double)M_ - mean*mean;
    if (var < 0.0) var = 0.0;
    float rs = (float)(1.0 / sqrt(var + (double)EPS_));
    float a  = gam[c]*rs;
    g_an[c] = a;
    g_bn[c] = bet[c] - (float)mean*a;
}

// ---------------- final: out = bn3(t3) + xc ----------------
__global__ void final_add_kernel(float* __restrict__ out) {
    int idx = blockIdx.x*blockDim.x + threadIdx.x;
    if (idx >= M_*C_) return;
    int c = idx % C_;
    out[idx] = g_t3[idx]*g_an[c] + g_bn[c] + g_xc[idx];
}

// =======================================================================================
extern "C" void kernel_launch(void* const* d_in, const int* in_sizes, int n_in,
                              void* d_out, int out_size) {
    const float* x        = (const float*)d_in[0];
    const float* dc_weight= (const float*)d_in[1];
    const float* dc_bias  = (const float*)d_in[2];
    const float* dc_p1w   = (const float*)d_in[3];
    const float* dc_p1b   = (const float*)d_in[4];
    const float* dc_p2w   = (const float*)d_in[5];
    const float* dc_p2b   = (const float*)d_in[6];
    const float* at_qw    = (const float*)d_in[7];
    const float* at_qb    = (const float*)d_in[8];
    const float* at_kvw   = (const float*)d_in[9];
    const float* at_kvb   = (const float*)d_in[10];
    const float* at_lcw   = (const float*)d_in[11];
    const float* at_lcb   = (const float*)d_in[12];
    const float* pj_dww   = (const float*)d_in[13];
    const float* pj_dwb   = (const float*)d_in[14];
    const float* pj_bn1g  = (const float*)d_in[15];
    const float* pj_bn1b  = (const float*)d_in[16];
    const float* pj_c1w   = (const float*)d_in[17];
    const float* pj_c1b   = (const float*)d_in[18];
    const float* pj_bn2g  = (const float*)d_in[19];
    const float* pj_bn2b  = (const float*)d_in[20];
    const float* pj_c2w   = (const float*)d_in[21];
    const float* pj_c2b   = (const float*)d_in[22];
    const float* pj_bn3g  = (const float*)d_in[23];
    const float* pj_bn3b  = (const float*)d_in[24];
    float* out = (float*)d_out;

    float *pq, *pkvin, *pkv, *pt1, *pt2, *pt3, *pan, *pbn;
    cudaGetSymbolAddress((void**)&pq,    g_q);
    cudaGetSymbolAddress((void**)&pkvin, g_kvin);
    cudaGetSymbolAddress((void**)&pkv,   g_kv);
    cudaGetSymbolAddress((void**)&pt1,   g_t1);
    cudaGetSymbolAddress((void**)&pt2,   g_t2);
    cudaGetSymbolAddress((void**)&pt3,   g_t3);
    cudaGetSymbolAddress((void**)&pan,   g_an);
    cudaGetSymbolAddress((void**)&pbn,   g_bn);

    // ---- branch 1: dynamic conv ----
    pooled_kernel<<<B_*K_, C2_>>>(x);
    dcmlp_kernel<<<B_, C2_>>>(dc_p1w, dc_p1b, dc_p2w, dc_p2b, dc_weight, dc_bias);
    dconv_kernel<<<dim3(16, B_), C2_>>>(x);

    // ---- branch 2: attention ----
    kvin_kernel<<<dim3(16, B_), C2_>>>(x, at_lcw, at_lcb);
    gemm_kernel<<<dim3(125, 6), 256>>>(x + C2_, C_, at_qw, at_qb,
                                       pq, C2_, M_, C2_, C2_, nullptr, nullptr, 0);
    gemm_kernel<<<dim3(125, 12), 256>>>(pkvin, C2_, at_kvw, at_kvb,
                                        pkv, C_, M_, C_, C2_, nullptr, nullptr, 0);
    attn_kernel<<<dim3(16, H_, B_), 256>>>();

    // ---- projection: dw3 + gelu + bn1 ----
    pjdw_kernel<<<dim3(8, B_), C_>>>(pj_dww, pj_dwb);
    stats_finalize_kernel<<<3, 256>>>(64, C_, pj_bn1g, pj_bn1b);

    // ---- c1 (bn1 folded into A) + gelu ----
    gemm_kernel<<<dim3(125, 2), 256>>>(pt1, C_, pj_c1w, pj_c1b,
                                       pt2, PJIN_, M_, PJIN_, C_, pan, pbn, 1);
    stats_partial_kernel<<<64, PJIN_>>>(pt2, PJIN_);
    stats_finalize_kernel<<<1, 256>>>(64, PJIN_, pj_bn2g, pj_bn2b);

    // ---- c2 (bn2 folded into A) ----
    gemm_kernel<<<dim3(125, 12), 256>>>(pt2, PJIN_, pj_c2w, pj_c2b,
                                        pt3, C_, M_, C_, PJIN_, pan, pbn, 0);
    stats_partial_kernel<<<64, C_>>>(pt3, C_);
    stats_finalize_kernel<<<3, 256>>>(64, C_, pj_bn3g, pj_bn3b);

    // ---- bn3 + residual ----
    final_add_kernel<<<(M_*C_ + 255)/256, 256>>>(out);
}

// round 3
// speedup vs baseline: 5.1087x; 5.1087x over previous
#include <cuda_runtime.h>
#include <math.h>

#define B_    8
#define L_    999
#define C_    768
#define C2_   384
#define H_    8
#define HD_   48
#define K_    3
#define DCIN_ 96
#define PJIN_ 96
#define M_    (B_*L_)          /* 7992 tokens */
#define SCALE_ 0.14433756729740643f
#define EPS_   1e-5f

__device__ __forceinline__ float gelu_f(float v) {
    return 0.5f * v * (1.0f + erff(v * 0.7071067811865475f));
}

// ---------------- scratch (device globals; no allocation allowed) ----------------
__device__ float g_q    [(size_t)M_*C2_];
__device__ float g_kvin [(size_t)M_*C2_];
__device__ float g_kv   [(size_t)M_*C_];
__device__ float g_xc   [(size_t)M_*C_];
__device__ float g_t1   [(size_t)M_*C_];
__device__ float g_t2   [(size_t)M_*PJIN_];
__device__ float g_t3   [(size_t)M_*C_];
__device__ float g_wdyn [B_*C2_*K_];
__device__ float g_bdyn [B_*C2_];
__device__ float g_ps   [128*C_];
__device__ float g_ps2  [128*C_];
__device__ float g_an   [C_];
__device__ float g_bn   [C_];

// ---------------- stage 1: pooled partial sums (4-way split over rows) ----------------
__global__ void pooled_kernel(const float* __restrict__ x) {
    int blk = blockIdx.x;            // (b*3+kk)*4+sub
    int sub = blk & 3;
    int bk  = blk >> 2;
    int b   = bk / K_;
    int kk  = bk % K_;
    int c   = threadIdx.x;           // 384
    int r0 = kk*333 + sub*84;
    int r1 = kk*333 + min(sub*84 + 84, 333);
    const float* xb = x + (size_t)b*L_*C_ + c;
    float s = 0.f;
    for (int l = r0; l < r1; l++) s += xb[(size_t)l*C_];
    g_ps[(size_t)blk*C2_ + c] = s;
}

// ---------------- stage 2: dynamic-conv score MLP + softmax over G ----------------
__global__ void dcmlp_kernel(const float* __restrict__ p1w, const float* __restrict__ p1b,
                             const float* __restrict__ p2w, const float* __restrict__ p2b,
                             const float* __restrict__ dcw, const float* __restrict__ dcb) {
    int b   = blockIdx.x;
    int tid = threadIdx.x;                 // 384
    __shared__ float col[4][C2_];
    __shared__ float hid[4][DCIN_];
    __shared__ float sc [4][2*C2_];
    {
        float cc[3];
        #pragma unroll
        for (int kk = 0; kk < 3; kk++) {
            int base = (b*3+kk)*4;
            cc[kk] = (g_ps[(size_t)(base+0)*C2_+tid] + g_ps[(size_t)(base+1)*C2_+tid]
                    + g_ps[(size_t)(base+2)*C2_+tid] + g_ps[(size_t)(base+3)*C2_+tid]) * (1.0f/333.0f);
            col[kk][tid] = cc[kk];
        }
        col[3][tid] = (cc[0]+cc[1]+cc[2]) * (1.0f/3.0f);
    }
    __syncthreads();
    {
        int kk = tid / DCIN_;
        int i  = tid % DCIN_;
        float s = p1b[i];
        const float* wr = p1w + (size_t)i*C2_;
        #pragma unroll 8
        for (int c = 0; c < C2_; c++) s += wr[c]*col[kk][c];
        hid[kk][i] = gelu_f(s);
    }
    __syncthreads();
    for (int t = tid; t < 4*768; t += 384) {
        int kk = t / 768, o = t % 768;
        float s = p2b[o];
        const float* wr = p2w + (size_t)o*DCIN_;
        #pragma unroll 8
        for (int i = 0; i < DCIN_; i++) s += wr[i]*hid[kk][i];
        sc[kk][o] = s;
    }
    __syncthreads();
    {
        int c = tid;
        #pragma unroll
        for (int kk = 0; kk < 3; kk++) {
            float e0 = sc[kk][c], e1 = sc[kk][C2_+c];
            float mx = fmaxf(e0,e1);
            float a0 = expf(e0-mx), a1 = expf(e1-mx);
            float inv = 1.f/(a0+a1);
            g_wdyn[(b*C2_+c)*3+kk] = (a0*dcw[c*3+kk] + a1*dcw[(C2_+c)*3+kk])*inv;
        }
        float e0 = sc[3][c], e1 = sc[3][C2_+c];
        float mx = fmaxf(e0,e1);
        float a0 = expf(e0-mx), a1 = expf(e1-mx);
        g_bdyn[b*C2_+c] = (a0*dcb[c] + a1*dcb[C2_+c])/(a0+a1);
    }
}

// ---------------- stage 3: dynamic depthwise conv -> xc[:, :, 0:384] (fully parallel) ----
__global__ void dconv_kernel(const float* __restrict__ x) {
    int b  = blockIdx.y;
    int tid = threadIdx.x;                 // 768: li 0..7, c4 0..95
    int l  = blockIdx.x*8 + (tid/96);
    int c  = (tid%96)*4;
    if (l >= L_) return;
    // weights for 4 channels: 12 consecutive floats, 16B aligned
    const float* wp = g_wdyn + ((size_t)b*C2_ + c)*3;
    float4 wA = *(const float4*)(wp);
    float4 wB = *(const float4*)(wp+4);
    float4 wC = *(const float4*)(wp+8);
    float4 bv = *(const float4*)(g_bdyn + (size_t)b*C2_ + c);
    const float* xb = x + ((size_t)b*L_ + l)*C_ + c;
    float4 zero = make_float4(0.f,0.f,0.f,0.f);
    float4 xm = (l > 0)      ? *(const float4*)(xb - C_) : zero;
    float4 x0 = *(const float4*)(xb);
    float4 xp = (l+1 < L_)   ? *(const float4*)(xb + C_) : zero;
    float4 r;
    r.x = xm.x*wA.x + x0.x*wA.y + xp.x*wA.z + bv.x;
    r.y = xm.y*wA.w + x0.y*wB.x + xp.y*wB.y + bv.y;
    r.z = xm.z*wB.z + x0.z*wB.w + xp.z*wC.x + bv.z;
    r.w = xm.w*wC.y + x0.w*wC.z + xp.w*wC.w + bv.w;
    *(float4*)(g_xc + ((size_t)b*L_ + l)*C_ + c) = r;
}

// ---------------- stage 4: kv_in = dw3(x2, lcw, lcb) + x2 (fully parallel) ----------------
__global__ void kvin_kernel(const float* __restrict__ x,
                            const float* __restrict__ lcw, const float* __restrict__ lcb) {
    int b  = blockIdx.y;
    int tid = threadIdx.x;                 // 768
    int l  = blockIdx.x*8 + (tid/96);
    int c  = (tid%96)*4;
    if (l >= L_) return;
    const float* wp = lcw + (size_t)c*3;
    float4 wA = *(const float4*)(wp);
    float4 wB = *(const float4*)(wp+4);
    float4 wC = *(const float4*)(wp+8);
    float4 bv = *(const float4*)(lcb + c);
    const float* xb = x + ((size_t)b*L_ + l)*C_ + C2_ + c;
    float4 zero = make_float4(0.f,0.f,0.f,0.f);
    float4 xm = (l > 0)      ? *(const float4*)(xb - C_) : zero;
    float4 x0 = *(const float4*)(xb);
    float4 xp = (l+1 < L_)   ? *(const float4*)(xb + C_) : zero;
    float4 r;
    r.x = xm.x*wA.x + x0.x*wA.y + xp.x*wA.z + bv.x + x0.x;
    r.y = xm.y*wA.w + x0.y*wB.x + xp.y*wB.y + bv.y + x0.y;
    r.z = xm.z*wB.z + x0.z*wB.w + xp.z*wC.x + bv.z + x0.z;
    r.w = xm.w*wC.y + x0.w*wC.z + xp.w*wC.w + bv.w + x0.w;
    *(float4*)(g_kvin + ((size_t)b*L_ + l)*C2_ + c) = r;
}

// ---------------- GEMM v2: 128x64 tile, 8x4 micro-tile, k-major smem --------------------
// C[m,n] = sum_k a(A[m,k]) * W[n,k] + bias[n] ; optional per-k affine on A, gelu epilogue
__global__ void gemm_kernel(const float* __restrict__ A, int lda,
                            const float* __restrict__ W,
                            const float* __restrict__ bias,
                            float* __restrict__ Cmat, int ldc,
                            int M, int N, int Kd,
                            const float* __restrict__ ascale,
                            const float* __restrict__ ashift,
                            int dogelu)
{
    __shared__ __align__(16) float As[16][132];
    __shared__ __align__(16) float Ws[16][68];
    int tid = threadIdx.x;                 // 256
    int tx = tid & 15, ty = tid >> 4;
    int m0 = blockIdx.x*128, n0 = blockIdx.y*64;
    float acc[8][4];
    #pragma unroll
    for (int i = 0; i < 8; i++)
        #pragma unroll
        for (int j = 0; j < 4; j++) acc[i][j] = 0.f;

    int alr = tid >> 1, alk = (tid & 1) << 3;    // A: row 0..127, k-offset 0/8
    int wlr = tid >> 2, wlk = (tid & 3) << 2;    // W: row 0..63,  k-offset 0/4/8/12
    float4 zero = make_float4(0.f,0.f,0.f,0.f);

    for (int k0 = 0; k0 < Kd; k0 += 16) {
        float4 a0 = zero, a1 = zero, w0 = zero;
        int gm = m0 + alr;
        if (gm < M) {
            const float* ap = A + (size_t)gm*lda + k0 + alk;
            a0 = *(const float4*)(ap);
            a1 = *(const float4*)(ap+4);
        }
        if (ascale) {
            int kb = k0 + alk;
            a0.x = a0.x*ascale[kb+0] + ashift[kb+0];
            a0.y = a0.y*ascale[kb+1] + ashift[kb+1];
            a0.z = a0.z*ascale[kb+2] + ashift[kb+2];
            a0.w = a0.w*ascale[kb+3] + ashift[kb+3];
            a1.x = a1.x*ascale[kb+4] + ashift[kb+4];
            a1.y = a1.y*ascale[kb+5] + ashift[kb+5];
            a1.z = a1.z*ascale[kb+6] + ashift[kb+6];
            a1.w = a1.w*ascale[kb+7] + ashift[kb+7];
        }
        int gn = n0 + wlr;
        if (gn < N) w0 = *(const float4*)(W + (size_t)gn*Kd + k0 + wlk);
        __syncthreads();
        As[alk+0][alr]=a0.x; As[alk+1][alr]=a0.y; As[alk+2][alr]=a0.z; As[alk+3][alr]=a0.w;
        As[alk+4][alr]=a1.x; As[alk+5][alr]=a1.y; As[alk+6][alr]=a1.z; As[alk+7][alr]=a1.w;
        Ws[wlk+0][wlr]=w0.x; Ws[wlk+1][wlr]=w0.y; Ws[wlk+2][wlr]=w0.z; Ws[wlk+3][wlr]=w0.w;
        __syncthreads();
        #pragma unroll
        for (int k = 0; k < 16; k++) {
            float4 aA = *(float4*)&As[k][ty*8];
            float4 aB = *(float4*)&As[k][ty*8+4];
            float4 bb = *(float4*)&Ws[k][tx*4];
            acc[0][0]+=aA.x*bb.x; acc[0][1]+=aA.x*bb.y; acc[0][2]+=aA.x*bb.z; acc[0][3]+=aA.x*bb.w;
            acc[1][0]+=aA.y*bb.x; acc[1][1]+=aA.y*bb.y; acc[1][2]+=aA.y*bb.z; acc[1][3]+=aA.y*bb.w;
            acc[2][0]+=aA.z*bb.x; acc[2][1]+=aA.z*bb.y; acc[2][2]+=aA.z*bb.z; acc[2][3]+=aA.z*bb.w;
            acc[3][0]+=aA.w*bb.x; acc[3][1]+=aA.w*bb.y; acc[3][2]+=aA.w*bb.z; acc[3][3]+=aA.w*bb.w;
            acc[4][0]+=aB.x*bb.x; acc[4][1]+=aB.x*bb.y; acc[4][2]+=aB.x*bb.z; acc[4][3]+=aB.x*bb.w;
            acc[5][0]+=aB.y*bb.x; acc[5][1]+=aB.y*bb.y; acc[5][2]+=aB.y*bb.z; acc[5][3]+=aB.y*bb.w;
            acc[6][0]+=aB.z*bb.x; acc[6][1]+=aB.z*bb.y; acc[6][2]+=aB.z*bb.z; acc[6][3]+=aB.z*bb.w;
            acc[7][0]+=aB.w*bb.x; acc[7][1]+=aB.w*bb.y; acc[7][2]+=aB.w*bb.z; acc[7][3]+=aB.w*bb.w;
        }
    }
    int gn0 = n0 + tx*4;
    if (gn0 < N) {
        float b0 = bias[gn0], b1 = bias[gn0+1], b2 = bias[gn0+2], b3 = bias[gn0+3];
        #pragma unroll
        for (int i = 0; i < 8; i++) {
            int gm = m0 + ty*8 + i;
            if (gm >= M) break;
            float4 r;
            r.x = acc[i][0]+b0; r.y = acc[i][1]+b1; r.z = acc[i][2]+b2; r.w = acc[i][3]+b3;
            if (dogelu) { r.x=gelu_f(r.x); r.y=gelu_f(r.y); r.z=gelu_f(r.z); r.w=gelu_f(r.w); }
            *(float4*)(Cmat + (size_t)gm*ldc + gn0) = r;
        }
    }
}

// ---------------- stage 7: flash attention v2 -> xc[:, :, 384:768] ----------------
// Output write reproduces the reference's transpose+flat-reshape reinterpretation:
// (c = h*HD+d, l) -> flat = c*L + l -> xc[b, flat/C2, C2 + flat%C2].
__global__ void attn_kernel() {
    int qt = blockIdx.x;     // 16 q tiles of 64
    int h  = blockIdx.y;
    int b  = blockIdx.z;
    int tid = threadIdx.x;   // 256
    int tx = tid & 15, ty = tid >> 4;

    __shared__ __align__(16) float qs[48*68];      // q transposed [d][q]
    __shared__ __align__(16) float un[64*65];      // union: ks_t [d][k] (stride 68) / ps [k][q] (stride 65)
    __shared__ __align__(16) float vs[64*52];      // v [k][d]

    const float* qb = g_q  + (size_t)b*L_*C2_ + h*HD_;
    const float* kb = g_kv + (size_t)b*L_*C_  + h*HD_;
    const float* vb = kb + C2_;

    int lr = tid >> 2;               // 0..63
    int d0 = (tid & 3) * 12;         // 0,12,24,36

    {   // load Q tile transposed
        int gl = qt*64 + lr;
        if (gl < L_) {
            #pragma unroll
            for (int t = 0; t < 3; t++) {
                float4 v = *(const float4*)(qb + (size_t)gl*C2_ + d0 + t*4);
                qs[(d0+t*4+0)*68+lr]=v.x; qs[(d0+t*4+1)*68+lr]=v.y;
                qs[(d0+t*4+2)*68+lr]=v.z; qs[(d0+t*4+3)*68+lr]=v.w;
            }
        } else {
            #pragma unroll
            for (int t = 0; t < 12; t++) qs[(d0+t)*68+lr]=0.f;
        }
    }

    float m[4], l[4], o[4][4], corr[4];
    #pragma unroll
    for (int i = 0; i < 4; i++) {
        m[i] = -1e30f; l[i] = 0.f;
        #pragma unroll
        for (int j = 0; j < 4; j++) o[i][j] = 0.f;
    }

    for (int kt = 0; kt < 16; kt++) {
        __syncthreads();   // prev stage2 done; safe to overwrite un/vs
        {
            int gl = kt*64 + lr;
            if (gl < L_) {
                #pragma unroll
                for (int t = 0; t < 3; t++) {
                    float4 kv = *(const float4*)(kb + (size_t)gl*C_ + d0 + t*4);
                    un[(d0+t*4+0)*68+lr]=kv.x; un[(d0+t*4+1)*68+lr]=kv.y;
                    un[(d0+t*4+2)*68+lr]=kv.z; un[(d0+t*4+3)*68+lr]=kv.w;
                    float4 vv = *(const float4*)(vb + (size_t)gl*C_ + d0 + t*4);
                    *(float4*)&vs[lr*52 + d0 + t*4] = vv;
                }
            } else {
                #pragma unroll
                for (int t = 0; t < 12; t++) un[(d0+t)*68+lr]=0.f;
                #pragma unroll
                for (int t = 0; t < 3; t++) *(float4*)&vs[lr*52 + d0 + t*4] = make_float4(0.f,0.f,0.f,0.f);
            }
        }
        __syncthreads();

        // ---- stage 1: S = Q^T K (4x4 micro-tile) ----
        float s[4][4];
        #pragma unroll
        for (int i = 0; i < 4; i++)
            #pragma unroll
            for (int j = 0; j < 4; j++) s[i][j] = 0.f;
        #pragma unroll 8
        for (int d = 0; d < 48; d++) {
            float4 aq = *(float4*)&qs[d*68 + ty*4];
            float4 ak = *(float4*)&un[d*68 + tx*4];
            s[0][0]+=aq.x*ak.x; s[0][1]+=aq.x*ak.y; s[0][2]+=aq.x*ak.z; s[0][3]+=aq.x*ak.w;
            s[1][0]+=aq.y*ak.x; s[1][1]+=aq.y*ak.y; s[1][2]+=aq.y*ak.z; s[1][3]+=aq.y*ak.w;
            s[2][0]+=aq.z*ak.x; s[2][1]+=aq.z*ak.y; s[2][2]+=aq.z*ak.z; s[2][3]+=aq.z*ak.w;
            s[3][0]+=aq.w*ak.x; s[3][1]+=aq.w*ak.y; s[3][2]+=aq.w*ak.z; s[3][3]+=aq.w*ak.w;
        }

        // ---- softmax (running, rows ty*4+i, reduce across 16 tx lanes) ----
        int gk0 = kt*64 + tx*4;
        #pragma unroll
        for (int i = 0; i < 4; i++) {
            #pragma unroll
            for (int j = 0; j < 4; j++)
                s[i][j] = (gk0 + j < L_) ? s[i][j]*SCALE_ : -1e30f;
            float mx = fmaxf(fmaxf(s[i][0],s[i][1]), fmaxf(s[i][2],s[i][3]));
            mx = fmaxf(mx, __shfl_xor_sync(0xffffffffu, mx, 1));
            mx = fmaxf(mx, __shfl_xor_sync(0xffffffffu, mx, 2));
            mx = fmaxf(mx, __shfl_xor_sync(0xffffffffu, mx, 4));
            mx = fmaxf(mx, __shfl_xor_sync(0xffffffffu, mx, 8));
            float mnew = fmaxf(m[i], mx);
            corr[i] = __expf(m[i] - mnew);
            m[i] = mnew;
            float lp = 0.f;
            #pragma unroll
            for (int j = 0; j < 4; j++) { s[i][j] = __expf(s[i][j]-mnew); lp += s[i][j]; }
            lp += __shfl_xor_sync(0xffffffffu, lp, 1);
            lp += __shfl_xor_sync(0xffffffffu, lp, 2);
            lp += __shfl_xor_sync(0xffffffffu, lp, 4);
            lp += __shfl_xor_sync(0xffffffffu, lp, 8);
            l[i] = l[i]*corr[i] + lp;
        }

        __syncthreads();   // stage1 reads of un done; safe to overwrite with P
        #pragma unroll
        for (int i = 0; i < 4; i++)
            #pragma unroll
            for (int j = 0; j < 4; j++)
                un[(tx*4+j)*65 + ty*4+i] = s[i][j];
        __syncthreads();

        // ---- stage 2: O += P V  (4q x 4d micro-tile; tx<12 covers d=48) ----
        if (tx < 12) {
            #pragma unroll
            for (int i = 0; i < 4; i++)
                #pragma unroll
                for (int j = 0; j < 4; j++) o[i][j] *= corr[i];
            #pragma unroll 4
            for (int k = 0; k < 64; k++) {
                float p0 = un[k*65 + ty*4+0];
                float p1 = un[k*65 + ty*4+1];
                float p2 = un[k*65 + ty*4+2];
                float p3 = un[k*65 + ty*4+3];
                float4 v = *(float4*)&vs[k*52 + tx*4];
                o[0][0]+=p0*v.x; o[0][1]+=p0*v.y; o[0][2]+=p0*v.z; o[0][3]+=p0*v.w;
                o[1][0]+=p1*v.x; o[1][1]+=p1*v.y; o[1][2]+=p1*v.z; o[1][3]+=p1*v.w;
                o[2][0]+=p2*v.x; o[2][1]+=p2*v.y; o[2][2]+=p2*v.z; o[2][3]+=p2*v.w;
                o[3][0]+=p3*v.x; o[3][1]+=p3*v.y; o[3][2]+=p3*v.z; o[3][3]+=p3*v.w;
            }
        }
    }

    if (tx < 12) {
        float* xcb = g_xc + (size_t)b*L_*C_;
        #pragma unroll
        for (int i = 0; i < 4; i++) {
            int gl = qt*64 + ty*4 + i;
            if (gl >= L_) continue;
            float inv = 1.f/l[i];
            #pragma unroll
            for (int j = 0; j < 4; j++) {
                int c = h*HD_ + tx*4 + j;
                int flat = c*L_ + gl;
                int lp2 = flat / C2_;
                int cp  = flat - lp2*C2_;
                xcb[(size_t)lp2*C_ + C2_ + cp] = o[i][j]*inv;
            }
        }
    }
}

// ---------------- stage 8a: t1 = gelu(dw3(xc)) (fully parallel) ----------------
__global__ void pjdw_kernel(const float* __restrict__ dww, const float* __restrict__ dwb) {
    int b  = blockIdx.y;
    int tid = threadIdx.x;                 // 768: li 0..3, c4 0..191
    int l  = blockIdx.x*4 + (tid/192);
    int c  = (tid%192)*4;
    if (l >= L_) return;
    const float* wp = dww + (size_t)c*3;
    float4 wA = *(const float4*)(wp);
    float4 wB = *(const float4*)(wp+4);
    float4 wC = *(const float4*)(wp+8);
    float4 bv = *(const float4*)(dwb + c);
    const float* xb = g_xc + ((size_t)b*L_ + l)*C_ + c;
    float4 zero = make_float4(0.f,0.f,0.f,0.f);
    float4 xm = (l > 0)    ? *(const float4*)(xb - C_) : zero;
    float4 x0 = *(const float4*)(xb);
    float4 xp = (l+1 < L_) ? *(const float4*)(xb + C_) : zero;
    float4 r;
    r.x = gelu_f(xm.x*wA.x + x0.x*wA.y + xp.x*wA.z + bv.x);
    r.y = gelu_f(xm.y*wA.w + x0.y*wB.x + xp.y*wB.y + bv.y);
    r.z = gelu_f(xm.z*wB.z + x0.z*wB.w + xp.z*wC.x + bv.z);
    r.w = gelu_f(xm.w*wC.y + x0.w*wC.z + xp.w*wC.w + bv.w);
    *(float4*)(g_t1 + ((size_t)b*L_ + l)*C_ + c) = r;
}

// ---------------- deterministic BN stats: partials + finalize -> affine (a,b) ----------
__global__ void stats_partial_kernel(const float* __restrict__ X, int Cch) {
    int blk = blockIdx.x;                  // 127 chunks of 63 rows
    int c   = threadIdx.x;
    int r0 = blk*63, r1 = min(r0+63, M_);
    float s = 0.f, s2 = 0.f;
    for (int r = r0; r < r1; r++) {
        float v = X[(size_t)r*Cch + c];
        s += v; s2 += v*v;
    }
    g_ps [(size_t)blk*Cch + c] = s;
    g_ps2[(size_t)blk*Cch + c] = s2;
}

__global__ void stats_finalize_kernel(int nblk, int Cch,
                                      const float* __restrict__ gam,
                                      const float* __restrict__ bet) {
    int c = blockIdx.x*blockDim.x + threadIdx.x;
    if (c >= Cch) return;
    double s = 0.0, s2 = 0.0;
    for (int i = 0; i < nblk; i++) { s += (double)g_ps[(size_t)i*Cch+c]; s2 += (double)g_ps2[(size_t)i*Cch+c]; }
    double mean = s / (double)M_;
    double var  = s2 / (double)M_ - mean*mean;
    if (var < 0.0) var = 0.0;
    float rs = (float)(1.0 / sqrt(var + (double)EPS_));
    float a  = gam[c]*rs;
    g_an[c] = a;
    g_bn[c] = bet[c] - (float)mean*a;
}

// ---------------- final: out = bn3(t3) + xc ----------------
__global__ void final_add_kernel(float* __restrict__ out) {
    int idx4 = blockIdx.x*blockDim.x + threadIdx.x;
    if (idx4 >= M_*C_/4) return;
    int idx = idx4*4;
    int c = idx % C_;
    float4 t = *(const float4*)(g_t3 + idx);
    float4 xv= *(const float4*)(g_xc + idx);
    float4 a = *(const float4*)(g_an + c);
    float4 bb= *(const float4*)(g_bn + c);
    float4 r;
    r.x = t.x*a.x + bb.x + xv.x;
    r.y = t.y*a.y + bb.y + xv.y;
    r.z = t.z*a.z + bb.z + xv.z;
    r.w = t.w*a.w + bb.w + xv.w;
    *(float4*)(out + idx) = r;
}

// =======================================================================================
extern "C" void kernel_launch(void* const* d_in, const int* in_sizes, int n_in,
                              void* d_out, int out_size) {
    const float* x        = (const float*)d_in[0];
    const float* dc_weight= (const float*)d_in[1];
    const float* dc_bias  = (const float*)d_in[2];
    const float* dc_p1w   = (const float*)d_in[3];
    const float* dc_p1b   = (const float*)d_in[4];
    const float* dc_p2w   = (const float*)d_in[5];
    const float* dc_p2b   = (const float*)d_in[6];
    const float* at_qw    = (const float*)d_in[7];
    const float* at_qb    = (const float*)d_in[8];
    const float* at_kvw   = (const float*)d_in[9];
    const float* at_kvb   = (const float*)d_in[10];
    const float* at_lcw   = (const float*)d_in[11];
    const float* at_lcb   = (const float*)d_in[12];
    const float* pj_dww   = (const float*)d_in[13];
    const float* pj_dwb   = (const float*)d_in[14];
    const float* pj_bn1g  = (const float*)d_in[15];
    const float* pj_bn1b  = (const float*)d_in[16];
    const float* pj_c1w   = (const float*)d_in[17];
    const float* pj_c1b   = (const float*)d_in[18];
    const float* pj_bn2g  = (const float*)d_in[19];
    const float* pj_bn2b  = (const float*)d_in[20];
    const float* pj_c2w   = (const float*)d_in[21];
    const float* pj_c2b   = (const float*)d_in[22];
    const float* pj_bn3g  = (const float*)d_in[23];
    const float* pj_bn3b  = (const float*)d_in[24];
    float* out = (float*)d_out;

    float *pq, *pkvin, *pkv, *pt1, *pt2, *pt3, *pan, *pbn;
    cudaGetSymbolAddress((void**)&pq,    g_q);
    cudaGetSymbolAddress((void**)&pkvin, g_kvin);
    cudaGetSymbolAddress((void**)&pkv,   g_kv);
    cudaGetSymbolAddress((void**)&pt1,   g_t1);
    cudaGetSymbolAddress((void**)&pt2,   g_t2);
    cudaGetSymbolAddress((void**)&pt3,   g_t3);
    cudaGetSymbolAddress((void**)&pan,   g_an);
    cudaGetSymbolAddress((void**)&pbn,   g_bn);

    // ---- branch 1: dynamic conv ----
    pooled_kernel<<<96, C2_>>>(x);
    dcmlp_kernel<<<B_, C2_>>>(dc_p1w, dc_p1b, dc_p2w, dc_p2b, dc_weight, dc_bias);
    dconv_kernel<<<dim3(125, B_), 768>>>(x);

    // ---- branch 2: attention ----
    kvin_kernel<<<dim3(125, B_), 768>>>(x, at_lcw, at_lcb);
    gemm_kernel<<<dim3(63, 6), 256>>>(x + C2_, C_, at_qw, at_qb,
                                      pq, C2_, M_, C2_, C2_, nullptr, nullptr, 0);
    gemm_kernel<<<dim3(63, 12), 256>>>(pkvin, C2_, at_kvw, at_kvb,
                                       pkv, C_, M_, C_, C2_, nullptr, nullptr, 0);
    attn_kernel<<<dim3(16, H_, B_), 256>>>();

    // ---- projection: dw3 + gelu, then BN1 stats ----
    pjdw_kernel<<<dim3(250, B_), 768>>>(pj_dww, pj_dwb);
    stats_partial_kernel<<<127, C_>>>(pt1, C_);
    stats_finalize_kernel<<<3, 256>>>(127, C_, pj_bn1g, pj_bn1b);

    // ---- c1 (bn1 folded into A) + gelu ----
    gemm_kernel<<<dim3(63, 2), 256>>>(pt1, C_, pj_c1w, pj_c1b,
                                      pt2, PJIN_, M_, PJIN_, C_, pan, pbn, 1);
    stats_partial_kernel<<<127, PJIN_>>>(pt2, PJIN_);
    stats_finalize_kernel<<<1, 256>>>(127, PJIN_, pj_bn2g, pj_bn2b);

    // ---- c2 (bn2 folded into A) ----
    gemm_kernel<<<dim3(63, 12), 256>>>(pt2, PJIN_, pj_c2w, pj_c2b,
                                       pt3, C_, M_, C_, PJIN_, pan, pbn, 0);
    stats_partial_kernel<<<127, C_>>>(pt3, C_);
    stats_finalize_kernel<<<3, 256>>>(127, C_, pj_bn3g, pj_bn3b);

    // ---- bn3 + residual ----
    final_add_kernel<<<(M_*C_/4 + 255)/256, 256>>>(out);
}